// round 15
// baseline (speedup 1.0000x reference)
#include <cuda_runtime.h>
#include <cstdint>

#define N      8192
#define NNZv   262144
#define NSEEDS 256
#define SAMP   7372            /* int(N * 0.9) */

// ---------------- scratch (device globals; no allocation allowed) ----------
struct Scratch {
    int   seed0[N];
    int   mask1[N];
    int   masknodes[N];
    float deg[N];          // 0.0f == all-zero bytes
};
__device__ Scratch       g_s;
__device__ float         g_norm[N];
__device__ int           g_maskidx[N];
__device__ int           g_temnum;
__device__ unsigned char g_keep[NNZv];   // fully written by k_bfs0

// ---------------- Threefry-2x32 (exact JAX reference rounds) ---------------
__host__ __device__ __forceinline__ void threefry(uint32_t key0, uint32_t key1,
                                                  uint32_t x0, uint32_t x1,
                                                  uint32_t &o0, uint32_t &o1) {
    uint32_t ks0 = key0, ks1 = key1, ks2 = key0 ^ key1 ^ 0x1BD11BDAu;
    x0 += ks0; x1 += ks1;
#define TF_ROT(v,d) (((v) << (d)) | ((v) >> (32 - (d))))
#define TF_R(r) { x0 += x1; x1 = TF_ROT(x1, r); x1 ^= x0; }
    TF_R(13) TF_R(15) TF_R(26) TF_R(6)   x0 += ks1; x1 += ks2 + 1u;
    TF_R(17) TF_R(29) TF_R(16) TF_R(24)  x0 += ks2; x1 += ks0 + 2u;
    TF_R(13) TF_R(15) TF_R(26) TF_R(6)   x0 += ks0; x1 += ks1 + 3u;
    TF_R(17) TF_R(29) TF_R(16) TF_R(24)  x0 += ks1; x1 += ks2 + 4u;
    TF_R(13) TF_R(15) TF_R(26) TF_R(6)   x0 += ks2; x1 += ks0 + 5u;
    o0 = x0; o1 = x1;
#undef TF_R
#undef TF_ROT
}

__device__ __forceinline__ float bits_to_uniform(uint32_t b) {
    return __uint_as_float((b >> 9) | 0x3F800000u) - 1.0f;
}

// ---------------- TMA bulk-store zero fill (R13-proven config) --------------
// Each block: zero a 16 KB SMEM buffer once, then TMA-bulk-store 16 chunks of
// 16 KB to its contiguous 256 KB slice. Write path = TMA engine (UTMASTG).
#define ZTPB    128
#define ZGRID   1024           /* per half: 1024 * 256KB = 256 MB */
#define ZCHUNK  16384          /* bytes per bulk store */
#define ZCHUNKS 16             /* chunks per block */

__global__ void __launch_bounds__(ZTPB)
k_zero_tma(char* __restrict__ out) {
    __shared__ __align__(128) float4 buf[ZCHUNK / 16];   // 16 KB
    int t = threadIdx.x;
    const float4 z = make_float4(0.f, 0.f, 0.f, 0.f);
#pragma unroll
    for (int i = t; i < ZCHUNK / 16; i += ZTPB)
        buf[i] = z;
    __syncthreads();

    if (t == 0) {
        // generic -> async-proxy ordering for the SMEM zeroes
        asm volatile("fence.proxy.async.shared::cta;" ::: "memory");
        uint32_t saddr;
        asm("{ .reg .u64 tmp; cvta.to.shared.u64 tmp, %1; cvt.u32.u64 %0, tmp; }"
            : "=r"(saddr) : "l"(buf));
        char* base = out + (size_t)blockIdx.x * (ZCHUNK * ZCHUNKS);
#pragma unroll
        for (int k = 0; k < ZCHUNKS; k++) {
            asm volatile(
                "cp.async.bulk.global.shared::cta.bulk_group [%0], [%1], %2;"
                :: "l"(base + (size_t)k * ZCHUNK), "r"(saddr), "n"(ZCHUNK)
                : "memory");
            asm volatile("cp.async.bulk.commit_group;" ::: "memory");
        }
        // all bulk stores complete (writes visible) before block exit
        asm volatile("cp.async.bulk.wait_group 0;" ::: "memory");
    }
    __syncthreads();
}

// ---------------- chain kernels --------------------------------------------

__global__ void k_seed_samp(const int* __restrict__ seeds, uint32_t t0, uint32_t t1) {
    int i = blockIdx.x * blockDim.x + threadIdx.x;
    if (i < NSEEDS) { int s = seeds[i]; g_s.seed0[s] = 1; g_s.masknodes[s] = 1; }
    if (i < SAMP) {
        uint32_t a, b; threefry(t0, t1, 0u, (uint32_t)i, a, b);
        g_s.masknodes[(a ^ b) & (N - 1)] = 1;
    }
}

__global__ void k_bfs0(const int* __restrict__ rows, const int* __restrict__ cols) {
    int e = blockIdx.x * blockDim.x + threadIdx.x;
    if (e >= NNZv) return;
    int r = rows[e], c = cols[e];
    bool inc = (g_s.seed0[r] | g_s.seed0[c]) != 0;
    g_keep[e] = inc ? 0 : 1;
    if (inc) { g_s.mask1[r] = 1; g_s.mask1[c] = 1; }
}

__global__ void k_bfs1_deg(const int* __restrict__ rows, const int* __restrict__ cols,
                           const float* __restrict__ comp) {
    int e = blockIdx.x * blockDim.x + threadIdx.x;
    if (e >= NNZv) return;
    if (!g_keep[e]) return;
    int r = rows[e], c = cols[e];
    if (g_s.mask1[r] | g_s.mask1[c]) { g_keep[e] = 0; return; }
    atomicAdd(&g_s.deg[r], comp[(size_t)r * N + c]);
}

__global__ void k_scan_norm() {
    __shared__ int warp_sums[32];
    int t    = threadIdx.x;
    int lane = t & 31;
    int wid  = t >> 5;
    int base = t * 8;

    int bits = 0, loc = 0;
#pragma unroll
    for (int i = 0; i < 8; i++) {
        g_norm[base + i] = rsqrtf(g_s.deg[base + i] + 1e-12f);
        int m = (g_s.masknodes[base + i] | g_s.mask1[base + i]) ? 1 : 0;
        bits |= m << i; loc += m;
    }

    int inc = loc;
#pragma unroll
    for (int off = 1; off < 32; off <<= 1) {
        int v = __shfl_up_sync(0xFFFFFFFFu, inc, off);
        if (lane >= off) inc += v;
    }
    if (lane == 31) warp_sums[wid] = inc;
    __syncthreads();

    if (wid == 0) {
        int v = warp_sums[lane];
        int s = v;
#pragma unroll
        for (int off = 1; off < 32; off <<= 1) {
            int u = __shfl_up_sync(0xFFFFFFFFu, s, off);
            if (lane >= off) s += u;
        }
        warp_sums[lane] = s - v;     // exclusive warp offset
        if (lane == 31) g_temnum = s;
    }
    __syncthreads();

    int pos = warp_sums[wid] + inc - loc;
#pragma unroll
    for (int i = 0; i < 8; i++)
        if ((bits >> i) & 1) g_maskidx[pos++] = base + i;
}

// enc scatter: kept edges only (tiny after the 2-deep BFS; final tail kernel)
__global__ void k_scatter_enc(const int* __restrict__ rows, const int* __restrict__ cols,
                              const float* __restrict__ comp,
                              float* __restrict__ enc) {
    int e = blockIdx.x * blockDim.x + threadIdx.x;
    if (e >= NNZv || !g_keep[e]) return;
    int r = rows[e], c = cols[e];
    size_t idx = (size_t)r * N + c;
    enc[idx] = comp[idx] * g_norm[r] * g_norm[c];
}

// dec scatter: [0,NNZ) kept edges + diagonal, [NNZ,2*NNZ) random mask pairs
// (touches ONLY dec; runs concurrently with the enc-half fill)
__global__ void k_scatter_dec(const int* __restrict__ rows, const int* __restrict__ cols,
                              const float* __restrict__ comp,
                              float* __restrict__ dec,
                              uint32_t a0, uint32_t a1, uint32_t b0, uint32_t b1) {
    int i = blockIdx.x * blockDim.x + threadIdx.x;
    if (i < NNZv) {
        if (i < N) {
            size_t d = (size_t)i * N + i;
            dec[d] = comp[d];
        }
        if (g_keep[i]) {
            int r = rows[i], c = cols[i];
            size_t idx = (size_t)r * N + c;
            dec[idx] = comp[idx];
        }
    } else {
        int e = i - NNZv;
        float tn = (float)g_temnum;
        uint32_t p, q;
        threefry(a0, a1, 0u, (uint32_t)e, p, q);
        float u1 = bits_to_uniform(p ^ q);
        threefry(b0, b1, 0u, (uint32_t)e, p, q);
        float u2 = bits_to_uniform(p ^ q);
        int r = g_maskidx[(int)floorf(u1 * tn)];
        int c = g_maskidx[(int)floorf(u2 * tn)];
        size_t x = (size_t)r * N + c;
        size_t y = (size_t)c * N + r;
        dec[x] = comp[x];
        dec[y] = comp[y];
    }
}

// ---------------- launch ---------------------------------------------------
extern "C" void kernel_launch(void* const* d_in, const int* in_sizes, int n_in,
                              void* d_out, int out_size) {
    const int*   rows  = (const int*)d_in[0];
    const int*   cols  = (const int*)d_in[1];
    // d_in[2] = adj_values: unused by the reference output
    const int*   seeds = (const int*)d_in[3];
    const float* comp  = (const float*)d_in[4];

    float* enc = (float*)d_out;
    float* dec = enc + (size_t)N * N;

    // -------- lazily-created resources (no device memory; work unchanged)
    static cudaStream_t sFill = nullptr, sChain = nullptr;
    static cudaEvent_t  evFork = nullptr, evDec = nullptr,
                        evEnc = nullptr, evChain = nullptr;
    static void* scratch_ptr = nullptr;
    if (sFill == nullptr) {
        cudaStreamCreateWithFlags(&sFill,  cudaStreamNonBlocking);
        cudaStreamCreateWithFlags(&sChain, cudaStreamNonBlocking);
        cudaEventCreateWithFlags(&evFork,  cudaEventDisableTiming);
        cudaEventCreateWithFlags(&evDec,   cudaEventDisableTiming);
        cudaEventCreateWithFlags(&evEnc,   cudaEventDisableTiming);
        cudaEventCreateWithFlags(&evChain, cudaEventDisableTiming);
        cudaGetSymbolAddress(&scratch_ptr, g_s);
    }

    // -------- host-side Threefry key derivation (root key (0,42))
    uint32_t s10, s11, s20, s21, s30, s31, t0u, t1u, tmpa, tmpb;
    threefry(0u, 42u, 0u, 0u, s10, s11);   // k1 = split(root,3)[0]
    threefry(0u, 42u, 0u, 1u, s20, s21);   // k2 (uniform u1)
    threefry(0u, 42u, 0u, 2u, s30, s31);   // k3 (uniform u2)
    threefry(s10, s11, 0u, 0u, tmpa, tmpb);// randint split: hi-bits subkey (unused)
    threefry(s10, s11, 0u, 1u, t0u, t1u);  // randint split: lo-bits subkey
    (void)tmpa; (void)tmpb;

    const int T = 256;

    // ---- fork from the capture-origin stream
    cudaEventRecord(evFork, 0);
    cudaStreamWaitEvent(sFill,  evFork, 0);
    cudaStreamWaitEvent(sChain, evFork, 0);

    // ---- branch A (sFill): TMA bulk-store fill — DEC half first, then ENC
    k_zero_tma<<<ZGRID, ZTPB, 0, sFill>>>((char*)dec);
    cudaEventRecord(evDec, sFill);
    k_zero_tma<<<ZGRID, ZTPB, 0, sFill>>>((char*)enc);
    cudaEventRecord(evEnc, sFill);

    // ---- branch B (sChain): chain, then dec scatter (hidden under enc fill)
    cudaMemsetAsync(scratch_ptr, 0, sizeof(Scratch), sChain);
    k_seed_samp<<<(SAMP + T - 1) / T, T, 0, sChain>>>(seeds, t0u, t1u);
    k_bfs0     <<<NNZv / T, T, 0, sChain>>>(rows, cols);
    k_bfs1_deg <<<NNZv / T, T, 0, sChain>>>(rows, cols, comp);
    k_scan_norm<<<1, 1024, 0, sChain>>>();
    cudaStreamWaitEvent(sChain, evDec, 0);
    k_scatter_dec<<<(2 * NNZv) / T, T, 0, sChain>>>(rows, cols, comp, dec,
                                                    s20, s21, s30, s31);
    cudaEventRecord(evChain, sChain);

    // ---- join: tiny enc scatter is the only tail after the enc fill
    cudaStreamWaitEvent(0, evEnc,   0);
    cudaStreamWaitEvent(0, evChain, 0);
    k_scatter_enc<<<NNZv / T, T>>>(rows, cols, comp, enc);
}

// round 16
// speedup vs baseline: 1.0737x; 1.0737x over previous
#include <cuda_runtime.h>
#include <cstdint>

#define N      8192
#define NNZv   262144
#define NSEEDS 256
#define SAMP   7372            /* int(N * 0.9) */

// ---------------- scratch (device globals; no allocation allowed) ----------
struct Scratch {
    int   seed0[N];
    int   mask1[N];
    int   masknodes[N];
    float deg[N];          // 0.0f == all-zero bytes
};
__device__ Scratch       g_s;
__device__ float         g_norm[N];
__device__ int           g_maskidx[N];
__device__ int           g_temnum;
__device__ unsigned char g_keep[NNZv];   // fully written by k_bfs0

// ---------------- Threefry-2x32 (exact JAX reference rounds) ---------------
__host__ __device__ __forceinline__ void threefry(uint32_t key0, uint32_t key1,
                                                  uint32_t x0, uint32_t x1,
                                                  uint32_t &o0, uint32_t &o1) {
    uint32_t ks0 = key0, ks1 = key1, ks2 = key0 ^ key1 ^ 0x1BD11BDAu;
    x0 += ks0; x1 += ks1;
#define TF_ROT(v,d) (((v) << (d)) | ((v) >> (32 - (d))))
#define TF_R(r) { x0 += x1; x1 = TF_ROT(x1, r); x1 ^= x0; }
    TF_R(13) TF_R(15) TF_R(26) TF_R(6)   x0 += ks1; x1 += ks2 + 1u;
    TF_R(17) TF_R(29) TF_R(16) TF_R(24)  x0 += ks2; x1 += ks0 + 2u;
    TF_R(13) TF_R(15) TF_R(26) TF_R(6)   x0 += ks0; x1 += ks1 + 3u;
    TF_R(17) TF_R(29) TF_R(16) TF_R(24)  x0 += ks1; x1 += ks2 + 4u;
    TF_R(13) TF_R(15) TF_R(26) TF_R(6)   x0 += ks2; x1 += ks0 + 5u;
    o0 = x0; o1 = x1;
#undef TF_R
#undef TF_ROT
}

__device__ __forceinline__ float bits_to_uniform(uint32_t b) {
    return __uint_as_float((b >> 9) | 0x3F800000u) - 1.0f;
}

// ---------------- TMA bulk-store zero fill (R13-proven config) --------------
// Each block: zero a 16 KB SMEM buffer once, then TMA-bulk-store 16 chunks of
// 16 KB to its contiguous 256 KB slice. Write path = TMA engine (UTMASTG).
// Single launch covers the whole 512 MB output (2048 blocks).
#define ZTPB    128
#define ZGRID   2048           /* 2048 * 256KB = 512 MB */
#define ZCHUNK  16384          /* bytes per bulk store */
#define ZCHUNKS 16             /* chunks per block */

__global__ void __launch_bounds__(ZTPB)
k_zero_tma(char* __restrict__ out) {
    __shared__ __align__(128) float4 buf[ZCHUNK / 16];   // 16 KB
    int t = threadIdx.x;
    const float4 z = make_float4(0.f, 0.f, 0.f, 0.f);
#pragma unroll
    for (int i = t; i < ZCHUNK / 16; i += ZTPB)
        buf[i] = z;
    __syncthreads();

    if (t == 0) {
        // generic -> async-proxy ordering for the SMEM zeroes
        asm volatile("fence.proxy.async.shared::cta;" ::: "memory");
        uint32_t saddr;
        asm("{ .reg .u64 tmp; cvta.to.shared.u64 tmp, %1; cvt.u32.u64 %0, tmp; }"
            : "=r"(saddr) : "l"(buf));
        char* base = out + (size_t)blockIdx.x * (ZCHUNK * ZCHUNKS);
#pragma unroll
        for (int k = 0; k < ZCHUNKS; k++) {
            asm volatile(
                "cp.async.bulk.global.shared::cta.bulk_group [%0], [%1], %2;"
                :: "l"(base + (size_t)k * ZCHUNK), "r"(saddr), "n"(ZCHUNK)
                : "memory");
            asm volatile("cp.async.bulk.commit_group;" ::: "memory");
        }
        // all bulk stores complete (writes visible) before block exit
        asm volatile("cp.async.bulk.wait_group 0;" ::: "memory");
    }
    __syncthreads();
}

// ---------------- chain kernels --------------------------------------------

__global__ void k_seed_samp(const int* __restrict__ seeds, uint32_t t0, uint32_t t1) {
    int i = blockIdx.x * blockDim.x + threadIdx.x;
    if (i < NSEEDS) { int s = seeds[i]; g_s.seed0[s] = 1; g_s.masknodes[s] = 1; }
    if (i < SAMP) {
        uint32_t a, b; threefry(t0, t1, 0u, (uint32_t)i, a, b);
        g_s.masknodes[(a ^ b) & (N - 1)] = 1;
    }
}

__global__ void k_bfs0(const int* __restrict__ rows, const int* __restrict__ cols) {
    int e = blockIdx.x * blockDim.x + threadIdx.x;
    if (e >= NNZv) return;
    int r = rows[e], c = cols[e];
    bool inc = (g_s.seed0[r] | g_s.seed0[c]) != 0;
    g_keep[e] = inc ? 0 : 1;
    if (inc) { g_s.mask1[r] = 1; g_s.mask1[c] = 1; }
}

__global__ void k_bfs1_deg(const int* __restrict__ rows, const int* __restrict__ cols,
                           const float* __restrict__ comp) {
    int e = blockIdx.x * blockDim.x + threadIdx.x;
    if (e >= NNZv) return;
    if (!g_keep[e]) return;
    int r = rows[e], c = cols[e];
    if (g_s.mask1[r] | g_s.mask1[c]) { g_keep[e] = 0; return; }
    atomicAdd(&g_s.deg[r], comp[(size_t)r * N + c]);
}

__global__ void k_scan_norm() {
    __shared__ int warp_sums[32];
    int t    = threadIdx.x;
    int lane = t & 31;
    int wid  = t >> 5;
    int base = t * 8;

    int bits = 0, loc = 0;
#pragma unroll
    for (int i = 0; i < 8; i++) {
        g_norm[base + i] = rsqrtf(g_s.deg[base + i] + 1e-12f);
        int m = (g_s.masknodes[base + i] | g_s.mask1[base + i]) ? 1 : 0;
        bits |= m << i; loc += m;
    }

    int inc = loc;
#pragma unroll
    for (int off = 1; off < 32; off <<= 1) {
        int v = __shfl_up_sync(0xFFFFFFFFu, inc, off);
        if (lane >= off) inc += v;
    }
    if (lane == 31) warp_sums[wid] = inc;
    __syncthreads();

    if (wid == 0) {
        int v = warp_sums[lane];
        int s = v;
#pragma unroll
        for (int off = 1; off < 32; off <<= 1) {
            int u = __shfl_up_sync(0xFFFFFFFFu, s, off);
            if (lane >= off) s += u;
        }
        warp_sums[lane] = s - v;     // exclusive warp offset
        if (lane == 31) g_temnum = s;
    }
    __syncthreads();

    int pos = warp_sums[wid] + inc - loc;
#pragma unroll
    for (int i = 0; i < 8; i++)
        if ((bits >> i) & 1) g_maskidx[pos++] = base + i;
}

// fused tail scatter: NNZ threads, each does tem pair e + (e<N ? diagonal) +
// (keep[e] ? kept-edge writes to enc and dec). keep is ~empty after the
// 2-deep BFS, so the dominant cost is the tem-pair half.
__global__ void k_scatter(const int* __restrict__ rows, const int* __restrict__ cols,
                          const float* __restrict__ comp,
                          float* __restrict__ enc, float* __restrict__ dec,
                          uint32_t a0, uint32_t a1, uint32_t b0, uint32_t b1) {
    int e = blockIdx.x * blockDim.x + threadIdx.x;
    if (e >= NNZv) return;

    // random mask-node pair (symmetric) -> dec
    {
        float tn = (float)g_temnum;
        uint32_t p, q;
        threefry(a0, a1, 0u, (uint32_t)e, p, q);
        float u1 = bits_to_uniform(p ^ q);
        threefry(b0, b1, 0u, (uint32_t)e, p, q);
        float u2 = bits_to_uniform(p ^ q);
        int r = g_maskidx[(int)floorf(u1 * tn)];
        int c = g_maskidx[(int)floorf(u2 * tn)];
        size_t x = (size_t)r * N + c;
        size_t y = (size_t)c * N + r;
        dec[x] = comp[x];
        dec[y] = comp[y];
    }

    // self loop -> dec
    if (e < N) {
        size_t d = (size_t)e * N + e;
        dec[d] = comp[d];
    }

    // kept edge -> enc (normalized) + dec
    if (g_keep[e]) {
        int r = rows[e], c = cols[e];
        size_t idx = (size_t)r * N + c;
        float v = comp[idx];
        enc[idx] = v * g_norm[r] * g_norm[c];
        dec[idx] = v;
    }
}

// ---------------- launch ---------------------------------------------------
extern "C" void kernel_launch(void* const* d_in, const int* in_sizes, int n_in,
                              void* d_out, int out_size) {
    const int*   rows  = (const int*)d_in[0];
    const int*   cols  = (const int*)d_in[1];
    // d_in[2] = adj_values: unused by the reference output
    const int*   seeds = (const int*)d_in[3];
    const float* comp  = (const float*)d_in[4];

    float* enc = (float*)d_out;
    float* dec = enc + (size_t)N * N;

    // -------- lazily-created resources (no device memory; work unchanged)
    static cudaStream_t sFill = nullptr, sChain = nullptr;
    static cudaEvent_t  evFork = nullptr, evFill = nullptr, evChain = nullptr;
    static void* scratch_ptr = nullptr;
    if (sFill == nullptr) {
        cudaStreamCreateWithFlags(&sFill,  cudaStreamNonBlocking);
        cudaStreamCreateWithFlags(&sChain, cudaStreamNonBlocking);
        cudaEventCreateWithFlags(&evFork,  cudaEventDisableTiming);
        cudaEventCreateWithFlags(&evFill,  cudaEventDisableTiming);
        cudaEventCreateWithFlags(&evChain, cudaEventDisableTiming);
        cudaGetSymbolAddress(&scratch_ptr, g_s);
    }

    // -------- host-side Threefry key derivation (root key (0,42))
    uint32_t s10, s11, s20, s21, s30, s31, t0u, t1u, tmpa, tmpb;
    threefry(0u, 42u, 0u, 0u, s10, s11);   // k1 = split(root,3)[0]
    threefry(0u, 42u, 0u, 1u, s20, s21);   // k2 (uniform u1)
    threefry(0u, 42u, 0u, 2u, s30, s31);   // k3 (uniform u2)
    threefry(s10, s11, 0u, 0u, tmpa, tmpb);// randint split: hi-bits subkey (unused)
    threefry(s10, s11, 0u, 1u, t0u, t1u);  // randint split: lo-bits subkey
    (void)tmpa; (void)tmpb;

    const int T = 256;

    // ---- fork from the capture-origin stream
    cudaEventRecord(evFork, 0);
    cudaStreamWaitEvent(sFill,  evFork, 0);
    cudaStreamWaitEvent(sChain, evFork, 0);

    // ---- branch A (sFill): single TMA bulk-store fill of the whole output
    k_zero_tma<<<ZGRID, ZTPB, 0, sFill>>>((char*)d_out);
    cudaEventRecord(evFill, sFill);

    // ---- branch B (sChain): mask chain (hidden under the fill; streaming-
    //      friendly, low intensity — scattered traffic stays OFF this window)
    cudaMemsetAsync(scratch_ptr, 0, sizeof(Scratch), sChain);
    k_seed_samp<<<(SAMP + T - 1) / T, T, 0, sChain>>>(seeds, t0u, t1u);
    k_bfs0     <<<NNZv / T, T, 0, sChain>>>(rows, cols);
    k_bfs1_deg <<<NNZv / T, T, 0, sChain>>>(rows, cols, comp);
    k_scan_norm<<<1, 1024, 0, sChain>>>();
    cudaEventRecord(evChain, sChain);

    // ---- join: single fused scatter tail (NNZ threads, double duty)
    cudaStreamWaitEvent(0, evFill,  0);
    cudaStreamWaitEvent(0, evChain, 0);
    k_scatter<<<NNZv / T, T>>>(rows, cols, comp, enc, dec,
                               s20, s21, s30, s31);
}